// round 11
// baseline (speedup 1.0000x reference)
#include <cuda_runtime.h>
#include <cstdint>

#define En 4096
#define Bn 8
#define HEADS 32
#define Dh 128
#define CK 128               // k-floats per chunk
#define RB 16                // W rows per block
#define SN 4                 // pipeline stages
#define KS 2                 // k-splits per output row
#define KCH (En / (CK * KS)) // 16 chunks per block

typedef unsigned long long u64;

__device__ __align__(16) float g_qkv[3 * Bn * En];
__device__ __align__(16) float g_o[Bn * En];

__device__ __forceinline__ void fma2(u64 &d, u64 a, u64 b) {
    asm("fma.rn.f32x2 %0, %1, %2, %0;" : "+l"(d) : "l"(a), "l"(b));
}
__device__ __forceinline__ float2 unpack2(u64 v) {
    float2 r; asm("mov.b64 {%0,%1}, %2;" : "=f"(r.x), "=f"(r.y) : "l"(v)); return r;
}
__device__ __forceinline__ void cp16(uint32_t saddr, const float* g) {
    asm volatile("cp.async.cg.shared.global [%0], [%1], 16;" :: "r"(saddr), "l"(g));
}

struct SmemTiles {
    float w[SN][RB][CK];  // 4 x 8KB
    float x[SN][Bn][CK];  // 4 x 4KB
};                        // 48KB

// Block (256 thr, 8 warps): 16 rows x 8 batches over k-range [k0, k0+2048),
// 2 rows per warp; partial sums atomicAdd'ed into out.
__device__ __forceinline__ void gemm_block(const float* __restrict__ W,
                                           const float* __restrict__ X,
                                           float* __restrict__ out,
                                           int row0, int k0) {
    __shared__ SmemTiles sm;
    const int t = threadIdx.x;
    const int warp = t >> 5, lane = t & 31;

    uint32_t swb = (uint32_t)__cvta_generic_to_shared(&sm.w[0][0][0]);
    uint32_t sxb = (uint32_t)__cvta_generic_to_shared(&sm.x[0][0][0]);

    // per-stage: W = 512 x 16B units, x = 256 x 16B units; 256 threads
    const float* wg[2]; uint32_t wsm[2];
#pragma unroll
    for (int p = 0; p < 2; ++p) {
        int u = p * 256 + t, r = u >> 5, c = u & 31;
        wg[p] = W + (size_t)(row0 + r) * En + k0 + c * 4;
        wsm[p] = swb + u * 16;
    }
    const float* xg; uint32_t xsm;
    {
        int b = t >> 5, c = t & 31;
        xg = X + (size_t)b * En + k0 + c * 4;
        xsm = sxb + t * 16;
    }

    auto issue_stage = [&](int st, int kc) {
        int koff = kc * CK;
        uint32_t wo = st * (RB * CK * 4);
        uint32_t xo = st * (Bn * CK * 4);
        cp16(wsm[0] + wo, wg[0] + koff);
        cp16(wsm[1] + wo, wg[1] + koff);
        cp16(xsm + xo, xg + koff);
        asm volatile("cp.async.commit_group;");
    };

#pragma unroll
    for (int s = 0; s < SN - 1; ++s) issue_stage(s, s);

    u64 acc[16];  // [r(2)][b(8)] packed (even-k, odd-k)
#pragma unroll
    for (int i = 0; i < 16; ++i) acc[i] = 0ull;

    for (int i = 0; i < KCH; ++i) {
        asm volatile("cp.async.wait_group %0;" :: "n"(SN - 2));
        __syncthreads();

        int nk = i + SN - 1;
        if (nk < KCH) issue_stage(nk % SN, nk);
        else asm volatile("cp.async.commit_group;");

        int st = i % SN;
        longlong2 w0 = *reinterpret_cast<const longlong2*>(&sm.w[st][warp * 2 + 0][lane * 4]);
        longlong2 w1 = *reinterpret_cast<const longlong2*>(&sm.w[st][warp * 2 + 1][lane * 4]);
#pragma unroll
        for (int b = 0; b < 8; ++b) {
            longlong2 xv = *reinterpret_cast<const longlong2*>(&sm.x[st][b][lane * 4]);
            fma2(acc[0 + b], (u64)w0.x, (u64)xv.x);
            fma2(acc[8 + b], (u64)w1.x, (u64)xv.x);
            fma2(acc[0 + b], (u64)w0.y, (u64)xv.y);
            fma2(acc[8 + b], (u64)w1.y, (u64)xv.y);
        }
    }

    float vals[16];
#pragma unroll
    for (int i = 0; i < 16; ++i) {
        float2 p = unpack2(acc[i]);
        vals[i] = p.x + p.y;
    }

    // butterfly transpose-reduce (16 values across 32 lanes)
    int n = 16;
#pragma unroll
    for (int m = 1; m <= 8; m <<= 1) {
        n >>= 1;
        bool up = (lane & m) != 0;
#pragma unroll
        for (int i = 0; i < n; ++i) {
            float keep = up ? vals[i + n] : vals[i];
            float send = up ? vals[i] : vals[i + n];
            keep += __shfl_xor_sync(0xffffffffu, send, m);
            vals[i] = keep;
        }
    }
    vals[0] += __shfl_xor_sync(0xffffffffu, vals[0], 16);

    if (lane < 16) {
        int j = ((lane & 1) << 3) | ((lane & 2) << 1) | ((lane >> 1) & 2) | ((lane >> 3) & 1);
        int r = j >> 3;
        int b = j & 7;
        atomicAdd(&out[(size_t)b * En + row0 + warp * 2 + r], vals[0]);
    }
}

// zero g_qkv (24576 float4 over 8192 threads)
__global__ void __launch_bounds__(256)
init_kernel() {
    int i = blockIdx.x * 256 + threadIdx.x;
    float4 z = make_float4(0.f, 0.f, 0.f, 0.f);
    float4* q4 = reinterpret_cast<float4*>(g_qkv);
#pragma unroll
    for (int p = 0; p < 3; ++p) q4[p * 8192 + i] = z;
}

// grid (512, 3): blockIdx.x = rowblock*2 + ksplit; blockIdx.y = projection
__global__ void __launch_bounds__(256, 4)
qkv_kernel(const float* __restrict__ Wq, const float* __restrict__ Wk,
           const float* __restrict__ Wv, const float* __restrict__ x) {
    int rb = blockIdx.x >> 1, ks = blockIdx.x & 1;
    const float* W = (blockIdx.y == 0) ? Wq : ((blockIdx.y == 1) ? Wk : Wv);
    gemm_block(W, x, g_qkv + blockIdx.y * (Bn * En), rb * RB, ks * (En / KS));
}

// Attention with all-ones KV cache collapses to o[d] = c1 + c2 * v[d] per (b,h).
// Also zero-initializes d_out for oproj's atomic accumulation.
__global__ void __launch_bounds__(256)
attn_kernel(float* __restrict__ out) {
    int gtid = blockIdx.x * blockDim.x + threadIdx.x;
    reinterpret_cast<float4*>(out)[gtid] = make_float4(0.f, 0.f, 0.f, 0.f);

    int warp = gtid >> 5;
    int lane = gtid & 31;
    int b = warp >> 5;
    int h = warp & 31;

    const float4* q4 = reinterpret_cast<const float4*>(g_qkv + (0 * Bn + b) * En + h * Dh);
    const float4* k4 = reinterpret_cast<const float4*>(g_qkv + (1 * Bn + b) * En + h * Dh);
    const float4* v4 = reinterpret_cast<const float4*>(g_qkv + (2 * Bn + b) * En + h * Dh);

    float4 qv = q4[lane];
    float4 kv = k4[lane];
    float4 vv = v4[lane];

    float sq = qv.x + qv.y + qv.z + qv.w;
    float dp = qv.x * kv.x + qv.y * kv.y + qv.z * kv.z + qv.w * kv.w;
#pragma unroll
    for (int m = 16; m >= 1; m >>= 1) {
        sq += __shfl_xor_sync(0xffffffffu, sq, m);
        dp += __shfl_xor_sync(0xffffffffu, dp, m);
    }

    const float scale = 0.08838834764831845f;  // 1/sqrt(128)
    float s0 = sq * scale;
    float sL = dp * scale;
    float mx = fmaxf(s0, sL);
    float e0 = expf(s0 - mx);
    float eL = expf(sL - mx);
    float inv = 1.0f / (4095.0f * e0 + eL);
    float c1 = 4095.0f * e0 * inv;
    float c2 = eL * inv;

    float4* o4 = reinterpret_cast<float4*>(g_o + b * En + h * Dh);
    o4[lane] = make_float4(c1 + c2 * vv.x, c1 + c2 * vv.y,
                           c1 + c2 * vv.z, c1 + c2 * vv.w);
}

// grid 512: blockIdx.x = rowblock*2 + ksplit
__global__ void __launch_bounds__(256, 4)
oproj_kernel(const float* __restrict__ Wo, float* __restrict__ out) {
    int rb = blockIdx.x >> 1, ks = blockIdx.x & 1;
    gemm_block(Wo, g_o, out, rb * RB, ks * (En / KS));
}

extern "C" void kernel_launch(void* const* d_in, const int* in_sizes, int n_in,
                              void* d_out, int out_size) {
    const float* x  = (const float*)d_in[0];
    const float* Wq = (const float*)d_in[1];
    const float* Wk = (const float*)d_in[2];
    const float* Wv = (const float*)d_in[3];
    const float* Wo = (const float*)d_in[4];
    float* out = (float*)d_out;

    init_kernel<<<32, 256>>>();
    dim3 gq(512, 3);
    qkv_kernel<<<gq, 256>>>(Wq, Wk, Wv, x);
    attn_kernel<<<32, 256>>>(out);
    oproj_kernel<<<512, 256>>>(Wo, out);
}

// round 12
// speedup vs baseline: 1.2445x; 1.2445x over previous
#include <cuda_runtime.h>
#include <cstdint>

#define En 4096
#define Bn 8
#define HEADS 32
#define Dh 128
#define CK 128                // k-floats per compute chunk
#define RB 16                 // W rows per block
#define KS 8                  // k-splits per output row
#define KBLK (En / KS)        // 512 k per block
#define NCH (KBLK / CK)       // 4 chunks

typedef unsigned long long u64;

__device__ __align__(16) float g_qkv[3 * Bn * En];
__device__ __align__(16) float g_o[Bn * En];

struct Smem {
    float w[NCH][RB][CK];  // 32KB
    float x[Bn][KBLK];     // 16KB
};                         // 48KB static

__device__ __forceinline__ void fma2(u64 &d, u64 a, u64 b) {
    asm("fma.rn.f32x2 %0, %1, %2, %0;" : "+l"(d) : "l"(a), "l"(b));
}
__device__ __forceinline__ float2 unpack2(u64 v) {
    float2 r; asm("mov.b64 {%0,%1}, %2;" : "=f"(r.x), "=f"(r.y) : "l"(v)); return r;
}
__device__ __forceinline__ void cp16(uint32_t saddr, const float* g) {
    asm volatile("cp.async.cg.shared.global [%0], [%1], 16;" :: "r"(saddr), "l"(g));
}
__device__ __forceinline__ void gdc_wait() {
    asm volatile("griddepcontrol.wait;" ::: "memory");
}
__device__ __forceinline__ void gdc_launch_dep() {
    asm volatile("griddepcontrol.launch_dependents;" ::: "memory");
}

// epilogue: butterfly transpose-reduce of 32 per-thread partials, atomicAdd out
__device__ __forceinline__ void reduce_store(u64* acc, float* __restrict__ out,
                                             int row0, int warp, int lane) {
    float vals[32];
#pragma unroll
    for (int i = 0; i < 32; ++i) {
        float2 p = unpack2(acc[i]);
        vals[i] = p.x + p.y;
    }
    int n = 32;
#pragma unroll
    for (int m = 1; m <= 16; m <<= 1) {
        n >>= 1;
        bool up = (lane & m) != 0;
#pragma unroll
        for (int i = 0; i < n; ++i) {
            float keep = up ? vals[i + n] : vals[i];
            float send = up ? vals[i] : vals[i + n];
            keep += __shfl_xor_sync(0xffffffffu, send, m);
            vals[i] = keep;
        }
    }
    int j = ((lane & 1) << 4) | ((lane & 2) << 2) | (lane & 4) |
            ((lane >> 2) & 2) | ((lane >> 4) & 1);
    int r = j >> 3;
    int b = j & 7;
    atomicAdd(&out[(size_t)b * En + row0 + warp * 4 + r], vals[0]);
}

// Block (128 thr): 16 rows x 8 batches over [k0, k0+512).
// Bulk fill: ALL W+x cp.asyncs issued up front, ONE wait, barrier-free compute.
// If PDL: W issued before griddepcontrol.wait (independent), x after (dependent).
template <bool PDL>
__device__ __forceinline__ void gemm_block(const float* __restrict__ W,
                                           const float* __restrict__ X,
                                           float* __restrict__ out,
                                           int row0, int k0) {
    __shared__ Smem sm;
    const int t = threadIdx.x;
    const int warp = t >> 5, lane = t & 31;

    uint32_t swb = (uint32_t)__cvta_generic_to_shared(&sm.w[0][0][0]);
    uint32_t sxb = (uint32_t)__cvta_generic_to_shared(&sm.x[0][0]);

    // W: 2048 x 16B units (32KB), 16 per thread
#pragma unroll
    for (int p = 0; p < 16; ++p) {
        int u = p * 128 + t;
        int c = u >> 9, r = (u >> 5) & 15, col = u & 31;
        cp16(swb + u * 16, W + (size_t)(row0 + r) * En + k0 + c * CK + col * 4);
    }
    asm volatile("cp.async.commit_group;");

    if (PDL) gdc_wait();   // upstream results now visible (X may be produced data)

    // x: 1024 x 16B units (16KB), 8 per thread
#pragma unroll
    for (int p = 0; p < 8; ++p) {
        int u = p * 128 + t;
        int b = u >> 7, col = u & 127;
        cp16(sxb + u * 16, X + (size_t)b * En + k0 + col * 4);
    }
    asm volatile("cp.async.commit_group;");
    asm volatile("cp.async.wait_group 0;");
    __syncthreads();

    u64 acc[32];  // [r(4)][b(8)] packed (even-k, odd-k)
#pragma unroll
    for (int i = 0; i < 32; ++i) acc[i] = 0ull;

    // barrier-free compute over 4 chunks
#pragma unroll
    for (int c = 0; c < NCH; ++c) {
        longlong2 wv[4];
#pragma unroll
        for (int r = 0; r < 4; ++r)
            wv[r] = *reinterpret_cast<const longlong2*>(&sm.w[c][warp * 4 + r][lane * 4]);
#pragma unroll
        for (int b = 0; b < 8; ++b) {
            longlong2 xv = *reinterpret_cast<const longlong2*>(&sm.x[b][c * CK + lane * 4]);
#pragma unroll
            for (int r = 0; r < 4; ++r) {
                fma2(acc[r * 8 + b], (u64)wv[r].x, (u64)xv.x);
                fma2(acc[r * 8 + b], (u64)wv[r].y, (u64)xv.y);
            }
        }
    }

    reduce_store(acc, out, row0, warp, lane);
}

// zero g_qkv (24576 float4 over 8192 threads)
__global__ void __launch_bounds__(256)
init_kernel() {
    int i = blockIdx.x * 256 + threadIdx.x;
    float4 z = make_float4(0.f, 0.f, 0.f, 0.f);
    float4* q4 = reinterpret_cast<float4*>(g_qkv);
#pragma unroll
    for (int p = 0; p < 3; ++p) q4[p * 8192 + i] = z;
}

// grid (2048, 3): blockIdx.x = rowblock*8 + ksplit; blockIdx.y = projection
__global__ void __launch_bounds__(128, 4)
qkv_kernel(const float* __restrict__ Wq, const float* __restrict__ Wk,
           const float* __restrict__ Wv, const float* __restrict__ x) {
    gdc_launch_dep();  // let attn/oproj launch into our drain wave
    int rb = blockIdx.x >> 3, ks = blockIdx.x & 7;
    const float* W = (blockIdx.y == 0) ? Wq : ((blockIdx.y == 1) ? Wk : Wv);
    gemm_block<false>(W, x, g_qkv + blockIdx.y * (Bn * En), rb * RB, ks * KBLK);
}

// Attention with all-ones KV cache collapses to o[d] = c1 + c2 * v[d] per (b,h).
// Zeroes d_out (independent) BEFORE waiting on qkv.
__global__ void __launch_bounds__(256)
attn_kernel(float* __restrict__ out) {
    gdc_launch_dep();
    int gtid = blockIdx.x * blockDim.x + threadIdx.x;
    reinterpret_cast<float4*>(out)[gtid] = make_float4(0.f, 0.f, 0.f, 0.f);

    gdc_wait();  // g_qkv complete

    int warp = gtid >> 5;
    int lane = gtid & 31;
    int b = warp >> 5;
    int h = warp & 31;

    const float4* q4 = reinterpret_cast<const float4*>(g_qkv + (0 * Bn + b) * En + h * Dh);
    const float4* k4 = reinterpret_cast<const float4*>(g_qkv + (1 * Bn + b) * En + h * Dh);
    const float4* v4 = reinterpret_cast<const float4*>(g_qkv + (2 * Bn + b) * En + h * Dh);

    float4 qv = q4[lane];
    float4 kv = k4[lane];
    float4 vv = v4[lane];

    float sq = qv.x + qv.y + qv.z + qv.w;
    float dp = qv.x * kv.x + qv.y * kv.y + qv.z * kv.z + qv.w * kv.w;
#pragma unroll
    for (int m = 16; m >= 1; m >>= 1) {
        sq += __shfl_xor_sync(0xffffffffu, sq, m);
        dp += __shfl_xor_sync(0xffffffffu, dp, m);
    }

    const float scale = 0.08838834764831845f;  // 1/sqrt(128)
    float s0 = sq * scale;
    float sL = dp * scale;
    float mx = fmaxf(s0, sL);
    float e0 = expf(s0 - mx);
    float eL = expf(sL - mx);
    float inv = 1.0f / (4095.0f * e0 + eL);
    float c1 = 4095.0f * e0 * inv;
    float c2 = eL * inv;

    float4* o4 = reinterpret_cast<float4*>(g_o + b * En + h * Dh);
    o4[lane] = make_float4(c1 + c2 * vv.x, c1 + c2 * vv.y,
                           c1 + c2 * vv.z, c1 + c2 * vv.w);
}

// grid 2048: Wo streamed pre-wait; g_o consumed post-wait
__global__ void __launch_bounds__(128, 4)
oproj_kernel(const float* __restrict__ Wo, float* __restrict__ out) {
    int rb = blockIdx.x >> 3, ks = blockIdx.x & 7;
    gemm_block<true>(Wo, g_o, out, rb * RB, ks * KBLK);
}

extern "C" void kernel_launch(void* const* d_in, const int* in_sizes, int n_in,
                              void* d_out, int out_size) {
    const float* x  = (const float*)d_in[0];
    const float* Wq = (const float*)d_in[1];
    const float* Wk = (const float*)d_in[2];
    const float* Wv = (const float*)d_in[3];
    const float* Wo = (const float*)d_in[4];
    float* out = (float*)d_out;

    init_kernel<<<32, 256>>>();

    dim3 gq(2048, 3);
    qkv_kernel<<<gq, 128>>>(Wq, Wk, Wv, x);

    cudaLaunchAttribute at[1];
    at[0].id = cudaLaunchAttributeProgrammaticStreamSerialization;
    at[0].val.programmaticStreamSerializationAllowed = 1;

    cudaLaunchConfig_t cfg_attn = {};
    cfg_attn.gridDim = dim3(32);
    cfg_attn.blockDim = dim3(256);
    cfg_attn.attrs = at;
    cfg_attn.numAttrs = 1;
    cudaLaunchKernelEx(&cfg_attn, attn_kernel, out);

    cudaLaunchConfig_t cfg_opj = {};
    cfg_opj.gridDim = dim3(2048);
    cfg_opj.blockDim = dim3(128);
    cfg_opj.attrs = at;
    cfg_opj.numAttrs = 1;
    cudaLaunchKernelEx(&cfg_opj, oproj_kernel, (const float*)Wo, out);
}

// round 13
// speedup vs baseline: 1.3517x; 1.0861x over previous
#include <cuda_runtime.h>
#include <cstdint>

#define En 4096
#define Bn 8
#define HEADS 32
#define Dh 128
#define CK 128               // k-floats per chunk
#define RB 16                // W rows per block
#define SN 4                 // pipeline stages
#define KS 4                 // k-splits per output row
#define KCH (En / (CK * KS)) // 8 chunks per block

typedef unsigned long long u64;

// qkv partials: [ks][proj][b][4096]
__device__ __align__(16) float g_part[KS * 3 * Bn * En];
__device__ __align__(16) float g_o[Bn * En];

__device__ __forceinline__ void fma2(u64 &d, u64 a, u64 b) {
    asm("fma.rn.f32x2 %0, %1, %2, %0;" : "+l"(d) : "l"(a), "l"(b));
}
__device__ __forceinline__ float2 unpack2(u64 v) {
    float2 r; asm("mov.b64 {%0,%1}, %2;" : "=f"(r.x), "=f"(r.y) : "l"(v)); return r;
}
__device__ __forceinline__ void cp16(uint32_t saddr, const float* g) {
    asm volatile("cp.async.cg.shared.global [%0], [%1], 16;" :: "r"(saddr), "l"(g));
}
__device__ __forceinline__ void gdc_wait() {
    asm volatile("griddepcontrol.wait;" ::: "memory");
}
__device__ __forceinline__ void gdc_launch_dep() {
    asm volatile("griddepcontrol.launch_dependents;" ::: "memory");
}
#define COMMIT() asm volatile("cp.async.commit_group;")
#define WAITG(n) asm volatile("cp.async.wait_group %0;" :: "n"(n))

struct SmemTiles {
    float w[SN][RB][CK];  // 32KB
    float x[SN][Bn][CK];  // 16KB
};                        // 48KB

// butterfly transpose-reduce of 32 per-thread partials -> 1 value/lane
__device__ __forceinline__ float reduce32(u64* acc, int lane, int& r_out, int& b_out) {
    float vals[32];
#pragma unroll
    for (int i = 0; i < 32; ++i) {
        float2 p = unpack2(acc[i]);
        vals[i] = p.x + p.y;
    }
    int n = 32;
#pragma unroll
    for (int m = 1; m <= 16; m <<= 1) {
        n >>= 1;
        bool up = (lane & m) != 0;
#pragma unroll
        for (int i = 0; i < n; ++i) {
            float keep = up ? vals[i + n] : vals[i];
            float send = up ? vals[i] : vals[i + n];
            keep += __shfl_xor_sync(0xffffffffu, send, m);
            vals[i] = keep;
        }
    }
    int j = ((lane & 1) << 4) | ((lane & 2) << 2) | (lane & 4) |
            ((lane >> 2) & 2) | ((lane >> 4) & 1);
    r_out = j >> 3;
    b_out = j & 7;
    return vals[0];
}

// ---------- shared compute core (R7 engine, untouched) ----------
// descriptors for the per-thread copy slots
struct CopyDesc {
    const float* wg[4]; uint32_t wsm[4];
    const float* xg[2]; uint32_t xsm[2];
};

__device__ __forceinline__ void make_desc(CopyDesc& cd, SmemTiles& sm,
                                          const float* W, const float* X,
                                          int row0, int k0, int t) {
    uint32_t swb = (uint32_t)__cvta_generic_to_shared(&sm.w[0][0][0]);
    uint32_t sxb = (uint32_t)__cvta_generic_to_shared(&sm.x[0][0][0]);
#pragma unroll
    for (int p = 0; p < 4; ++p) {
        int u = p * 128 + t, r = u >> 5, c = u & 31;
        cd.wg[p] = W + (size_t)(row0 + r) * En + k0 + c * 4;
        cd.wsm[p] = swb + u * 16;
    }
#pragma unroll
    for (int p = 0; p < 2; ++p) {
        int u = p * 128 + t, b = u >> 5, c = u & 31;
        cd.xg[p] = X + (size_t)b * En + k0 + c * 4;
        cd.xsm[p] = sxb + u * 16;
    }
}
__device__ __forceinline__ void issue_w(CopyDesc& cd, int st, int kc) {
    int koff = kc * CK;
    uint32_t wo = st * (RB * CK * 4);
#pragma unroll
    for (int p = 0; p < 4; ++p) cp16(cd.wsm[p] + wo, cd.wg[p] + koff);
}
__device__ __forceinline__ void issue_x(CopyDesc& cd, int st, int kc) {
    int koff = kc * CK;
    uint32_t xo = st * (Bn * CK * 4);
#pragma unroll
    for (int p = 0; p < 2; ++p) cp16(cd.xsm[p] + xo, cd.xg[p] + koff);
}
__device__ __forceinline__ void consume_chunk(SmemTiles& sm, u64* acc,
                                              int st, int warp, int lane) {
    longlong2 wv[4];
#pragma unroll
    for (int r = 0; r < 4; ++r)
        wv[r] = *reinterpret_cast<const longlong2*>(&sm.w[st][warp * 4 + r][lane * 4]);
#pragma unroll
    for (int b = 0; b < 8; ++b) {
        longlong2 xv = *reinterpret_cast<const longlong2*>(&sm.x[st][b][lane * 4]);
#pragma unroll
        for (int r = 0; r < 4; ++r) {
            fma2(acc[r * 8 + b], (u64)wv[r].x, (u64)xv.x);
            fma2(acc[r * 8 + b], (u64)wv[r].y, (u64)xv.y);
        }
    }
}

// ---------- qkv: R7 pipeline, direct partial store ----------
__global__ void __launch_bounds__(128, 4)
qkv_kernel(const float* __restrict__ Wq, const float* __restrict__ Wk,
           const float* __restrict__ Wv, const float* __restrict__ x) {
    gdc_launch_dep();
    __shared__ SmemTiles sm;
    const int t = threadIdx.x, warp = t >> 5, lane = t & 31;
    int rb = blockIdx.x >> 2, ks = blockIdx.x & 3;
    int row0 = rb * RB, k0 = ks * (En / KS);
    const float* W = (blockIdx.y == 0) ? Wq : ((blockIdx.y == 1) ? Wk : Wv);
    float* out = g_part + (size_t)(ks * 3 + blockIdx.y) * Bn * En;

    CopyDesc cd;
    make_desc(cd, sm, W, x, row0, k0, t);

#pragma unroll
    for (int s = 0; s < SN - 1; ++s) { issue_w(cd, s, s); issue_x(cd, s, s); COMMIT(); }

    u64 acc[32];
#pragma unroll
    for (int i = 0; i < 32; ++i) acc[i] = 0ull;

    for (int i = 0; i < KCH; ++i) {
        WAITG(SN - 2);
        __syncthreads();
        int nk = i + SN - 1;
        if (nk < KCH) { issue_w(cd, nk % SN, nk); issue_x(cd, nk % SN, nk); COMMIT(); }
        else COMMIT();
        consume_chunk(sm, acc, i % SN, warp, lane);
    }

    int r, b;
    float v = reduce32(acc, lane, r, b);
    out[(size_t)b * En + row0 + warp * 4 + r] = v;
}

// ---------- attn: PDL; zeroes d_out pre-wait; sums partials ----------
__global__ void __launch_bounds__(256)
attn_kernel(float* __restrict__ out) {
    gdc_launch_dep();
    int gtid = blockIdx.x * blockDim.x + threadIdx.x;
    reinterpret_cast<float4*>(out)[gtid] = make_float4(0.f, 0.f, 0.f, 0.f);

    gdc_wait();  // all qkv partials written

    int warp = gtid >> 5;
    int lane = gtid & 31;
    int b = warp >> 5;
    int h = warp & 31;

    float4 qv = make_float4(0.f, 0.f, 0.f, 0.f);
    float4 kv = qv, vv = qv;
#pragma unroll
    for (int ksp = 0; ksp < KS; ++ksp) {
        size_t base = (size_t)(ksp * 3) * Bn * En + (size_t)b * En + h * Dh + lane * 4;
        float4 a0 = *reinterpret_cast<const float4*>(g_part + base);
        float4 a1 = *reinterpret_cast<const float4*>(g_part + base + (size_t)Bn * En);
        float4 a2 = *reinterpret_cast<const float4*>(g_part + base + (size_t)2 * Bn * En);
        qv.x += a0.x; qv.y += a0.y; qv.z += a0.z; qv.w += a0.w;
        kv.x += a1.x; kv.y += a1.y; kv.z += a1.z; kv.w += a1.w;
        vv.x += a2.x; vv.y += a2.y; vv.z += a2.z; vv.w += a2.w;
    }

    float sq = qv.x + qv.y + qv.z + qv.w;
    float dp = qv.x * kv.x + qv.y * kv.y + qv.z * kv.z + qv.w * kv.w;
#pragma unroll
    for (int m = 16; m >= 1; m >>= 1) {
        sq += __shfl_xor_sync(0xffffffffu, sq, m);
        dp += __shfl_xor_sync(0xffffffffu, dp, m);
    }

    const float scale = 0.08838834764831845f;  // 1/sqrt(128)
    float s0 = sq * scale;
    float sL = dp * scale;
    float mx = fmaxf(s0, sL);
    float e0 = expf(s0 - mx);
    float eL = expf(sL - mx);
    float inv = 1.0f / (4095.0f * e0 + eL);
    float c1 = 4095.0f * e0 * inv;
    float c2 = eL * inv;

    float4* o4 = reinterpret_cast<float4*>(g_o + b * En + h * Dh);
    o4[lane] = make_float4(c1 + c2 * vv.x, c1 + c2 * vv.y,
                           c1 + c2 * vv.z, c1 + c2 * vv.w);
}

// ---------- oproj: PDL; W prologue pre-wait, x after; R7 engine ----------
__global__ void __launch_bounds__(128, 4)
oproj_kernel(const float* __restrict__ Wo, float* __restrict__ out) {
    __shared__ SmemTiles sm;
    const int t = threadIdx.x, warp = t >> 5, lane = t & 31;
    int rb = blockIdx.x >> 2, ks = blockIdx.x & 3;
    int row0 = rb * RB, k0 = ks * (En / KS);

    CopyDesc cd;
    make_desc(cd, sm, Wo, g_o, row0, k0, t);

    // W prologue: 3 groups (independent of upstream)
#pragma unroll
    for (int s = 0; s < SN - 1; ++s) { issue_w(cd, s, s); COMMIT(); }

    gdc_wait();  // attn done -> g_o and zeroed out visible

    // x prologue: 3 more groups
#pragma unroll
    for (int s = 0; s < SN - 1; ++s) { issue_x(cd, s, s); COMMIT(); }

    u64 acc[32];
#pragma unroll
    for (int i = 0; i < 32; ++i) acc[i] = 0ull;

    // groups: [W0 W1 W2 X0 X1 X2 WX3 WX4 ... WX7]; stage i ready after group
    // idx (3+i) for i<3, (i+3) for i>=3. Pending-allowed at wait of iter i
    // (committed = 6 + min(i, KCH-3)): 2,2,2,2,2,2,1,0.
#pragma unroll
    for (int i = 0; i < KCH; ++i) {
        if (i < KCH - 2) WAITG(2);
        else if (i == KCH - 2) WAITG(1);
        else WAITG(0);
        __syncthreads();
        int nk = i + SN - 1;
        if (nk < KCH) { issue_w(cd, nk % SN, nk); issue_x(cd, nk % SN, nk); COMMIT(); }
        consume_chunk(sm, acc, i % SN, warp, lane);
    }

    int r, b;
    float v = reduce32(acc, lane, r, b);
    atomicAdd(&out[(size_t)b * En + row0 + warp * 4 + r], v);
}

extern "C" void kernel_launch(void* const* d_in, const int* in_sizes, int n_in,
                              void* d_out, int out_size) {
    const float* x  = (const float*)d_in[0];
    const float* Wq = (const float*)d_in[1];
    const float* Wk = (const float*)d_in[2];
    const float* Wv = (const float*)d_in[3];
    const float* Wo = (const float*)d_in[4];
    float* out = (float*)d_out;

    dim3 gq(1024, 3);
    qkv_kernel<<<gq, 128>>>(Wq, Wk, Wv, x);

    cudaLaunchAttribute at[1];
    at[0].id = cudaLaunchAttributeProgrammaticStreamSerialization;
    at[0].val.programmaticStreamSerializationAllowed = 1;

    cudaLaunchConfig_t cfg_attn = {};
    cfg_attn.gridDim = dim3(32);
    cfg_attn.blockDim = dim3(256);
    cfg_attn.attrs = at;
    cfg_attn.numAttrs = 1;
    cudaLaunchKernelEx(&cfg_attn, attn_kernel, out);

    cudaLaunchConfig_t cfg_opj = {};
    cfg_opj.gridDim = dim3(1024);
    cfg_opj.blockDim = dim3(128);
    cfg_opj.attrs = at;
    cfg_opj.numAttrs = 1;
    cudaLaunchKernelEx(&cfg_opj, oproj_kernel, (const float*)Wo, out);
}